// round 12
// baseline (speedup 1.0000x reference)
#include <cuda_runtime.h>
#include <cuda_fp16.h>
#include <cstdint>
#include <math.h>

// Shapes (fixed)
constexpr int NROW = 128;
constexpr int DDIM = 512;
constexpr int CDIM = 8192;
constexpr int NQ   = 32768;

// ---------------- device scratch ----------------
__device__ __align__(16) float g_s1[(size_t)NROW * NQ];
__device__ __align__(16) float g_s2[(size_t)NROW * NQ];
__device__ __align__(16) unsigned short g_a1[NROW * DDIM];   // fp16 normalized new_embeds
__device__ __align__(16) unsigned short g_a2[NROW * CDIM];   // fp16 new_logits
__device__ int   g_qlab[NQ];
__device__ float g_part[512 * 8];     // per (row, quarter): m1,l1,m2,l2,sw,s1w,s2w,cnt

// ---------------- small helpers ----------------
__device__ __forceinline__ uint32_t smem_u32(const void* p) {
    uint32_t a;
    asm("{ .reg .u64 t; cvta.to.shared.u64 t, %1; cvt.u32.u64 %0, t; }" : "=r"(a) : "l"(p));
    return a;
}
__device__ __forceinline__ void ldm4(uint32_t* r, uint32_t addr) {
    asm volatile("ldmatrix.sync.aligned.m8n8.x4.shared.b16 {%0,%1,%2,%3}, [%4];"
                 : "=r"(r[0]), "=r"(r[1]), "=r"(r[2]), "=r"(r[3]) : "r"(addr));
}
__device__ __forceinline__ void mma_f16(float* d, const uint32_t* a, const uint32_t* b) {
    asm volatile(
        "mma.sync.aligned.m16n8k16.row.col.f32.f16.f16.f32 "
        "{%0,%1,%2,%3}, {%4,%5,%6,%7}, {%8,%9}, {%0,%1,%2,%3};"
        : "+f"(d[0]), "+f"(d[1]), "+f"(d[2]), "+f"(d[3])
        : "r"(a[0]), "r"(a[1]), "r"(a[2]), "r"(a[3]), "r"(b[0]), "r"(b[1]));
}
#define CP16(saddr, gptr) \
    asm volatile("cp.async.ca.shared.global [%0], [%1], 16;" :: "r"(saddr), "l"(gptr))
#define CP_COMMIT() asm volatile("cp.async.commit_group;" ::: "memory")
#define CP_WAIT0()  asm volatile("cp.async.wait_group 0;" ::: "memory")

// ---------------- kernel: normalize new_embeds -> fp16 ----------------
__global__ void normalize_half(const float* __restrict__ x) {
    int i = blockIdx.x, tid = threadIdx.x;           // 128 threads
    const float* xr = x + (size_t)i * DDIM;
    float s = 0.f;
    for (int d = tid; d < DDIM; d += 128) { float v = xr[d]; s += v * v; }
    for (int o = 16; o; o >>= 1) s += __shfl_down_sync(0xffffffffu, s, o);
    __shared__ float sh[4];
    if ((tid & 31) == 0) sh[tid >> 5] = s;
    __syncthreads();
    __shared__ float invs;
    if (tid == 0) invs = 1.0f / fmaxf(sqrtf(sh[0] + sh[1] + sh[2] + sh[3]), 1e-12f);
    __syncthreads();
    float iv = invs;
    for (int d = tid; d < DDIM; d += 128)
        g_a1[i * DDIM + d] = __half_as_ushort(__float2half_rn(xr[d] * iv));
}

// ---------------- kernel: new_logits -> fp16 ----------------
__global__ void half_logits(const float* __restrict__ x) {
    int idx = (blockIdx.x * blockDim.x + threadIdx.x) * 4;   // over 128*8192
    float4 v = *(const float4*)(x + idx);
    __half2 h0 = __floats2half2_rn(v.x, v.y);
    __half2 h1 = __floats2half2_rn(v.z, v.w);
    uint2 p; p.x = *(uint32_t*)&h0; p.y = *(uint32_t*)&h1;
    *(uint2*)(g_a2 + idx) = p;
}

// ---------------- kernel: updated queue labels ----------------
__global__ void build_qlab(const int* __restrict__ ql, const int* __restrict__ labels,
                           const int* __restrict__ hdrp) {
    int j = blockIdx.x * blockDim.x + threadIdx.x;
    int hdr = *hdrp;
    int r = (j - hdr) & (NQ - 1);
    g_qlab[j] = (r < NROW) ? labels[r] : ql[j];
}

// ---------------- fused fp16 GEMMs: 4-stage ring, 1 barrier per 2 chunks ----------------
// blocks [0,256): out1 = A1 @ B1^T (K=DDIM, short, drains first)
// blocks [256,512): out2 = A2 @ B2^T (K=CDIM)
// CTA tile 128x128, BK=32; 8 warps (4M x 2N), warp tile 32x64.
// Super-iter s (chunks 2s, 2s+1):
//   issue cp.async {A,Bf32}(2s+2, 2s+3) -> compute(2s) -> compute(2s+1)
//   -> wait0 -> convert(2s+2), convert(2s+3) (own-thread data) -> __syncthreads.
constexpr int BPAD = 80;                 // fp16 tile row stride (conflict-free ldmatrix)
constexpr int SZ_T = 128 * BPAD;         // 10240 per fp16 tile stage
constexpr int SZ_F = 128 * 128;          // 16384 fp32 staging (128B rows, XOR-swizzled)
constexpr int O_A   = 0;                 // [4 stages x 10240]
constexpr int O_B16 = 4 * SZ_T;          // 40960 [4 stages x 10240]
constexpr int O_F   = 8 * SZ_T;          // 81920 [2 stages x 16384]
constexpr int GEMM_SMEM = O_F + 2 * SZ_F;    // 114688 (112KB) -> 2 CTAs/SM

__global__ __launch_bounds__(256, 2) void gemm_mma(
    const unsigned short* __restrict__ A1, const float* __restrict__ Bq1,
    const float* __restrict__ Bold1, float* __restrict__ out1, int K1,
    const unsigned short* __restrict__ A2, const float* __restrict__ Bq2,
    const float* __restrict__ Bold2, float* __restrict__ out2, int K2,
    const int* __restrict__ hdrp)
{
    extern __shared__ char smem[];
    const uint32_t sb = smem_u32(smem);
    const int tid = threadIdx.x, lane = tid & 31, wid = tid >> 5;
    const int wm = wid >> 1, wn = wid & 1;

    // select problem: short l1 blocks first (better backfill)
    const bool is1 = (blockIdx.x < 256);
    const int n0 = (is1 ? blockIdx.x : blockIdx.x - 256) * 128;
    const int K  = is1 ? K1 : K2;
    const unsigned short* A = is1 ? A1 : A2;
    const float* Bq   = is1 ? Bq1 : Bq2;
    const float* Bold = is1 ? Bold1 : Bold2;
    float* out = is1 ? out1 : out2;
    const int nch = K >> 5;

    // B gmem row with circular-queue redirect; 2 threads per row (seg = 64B half)
    const int rb = tid >> 1, seg = tid & 1;
    const int hdr = *hdrp;
    const int j = n0 + rb;
    const int r = (j - hdr) & (NQ - 1);
    const char* gBrow = (const char*)((r < NROW) ? (Bold + (size_t)r * K)
                                                 : (Bq + (size_t)j * K));
    const int rm = rb & 3;               // XOR-4 swizzle key for fp32 staging

    // A: 2 threads per row, 32B each
    const int arow = tid >> 1;
    const int acol = (tid & 1) * 32;
    const char* gA = (const char*)A + (size_t)arow * K * 2 + acol;
    const uint32_t sA = sb + O_A + arow * BPAD + acol;

    // ldmatrix lane addressing
    const int g = lane >> 3, lr = lane & 7;
    const uint32_t aRowOff = (uint32_t)(wm * 32 + (g & 1) * 8 + lr) * BPAD + (g >> 1) * 16;
    const uint32_t bRowOff = (uint32_t)(wn * 64 + (g >> 1) * 8 + lr) * BPAD + (g & 1) * 16;

    float acc[2][8][4];
#pragma unroll
    for (int mt = 0; mt < 2; mt++)
#pragma unroll
        for (int nt = 0; nt < 8; nt++)
#pragma unroll
            for (int u = 0; u < 4; u++) acc[mt][nt][u] = 0.f;

    auto cpA = [&](int c) {
        const char* s0 = gA + (size_t)c * 64;
        uint32_t d0 = sA + (c & 3) * SZ_T;
        CP16(d0, s0); CP16(d0 + 16, s0 + 16);
    };
    auto cpB = [&](int c) {
        const char* s0 = gBrow + (size_t)c * 128 + seg * 64;
        uint32_t base = sb + O_F + (c & 1) * SZ_F + rb * 128;
#pragma unroll
        for (int i = 0; i < 4; i++)
            CP16(base + (((seg * 4 + i) ^ rm) << 4), s0 + i * 16);
    };
    // convert chunk c: fp32 stage (c&1) -> fp16 tile stage (c&3); own-thread data only
    auto convertB = [&](int c) {
        const char* base = smem + O_F + (c & 1) * SZ_F + rb * 128;
        float4 f0 = *(const float4*)(base + (((seg * 4 + 0) ^ rm) << 4));
        float4 f1 = *(const float4*)(base + (((seg * 4 + 1) ^ rm) << 4));
        float4 f2 = *(const float4*)(base + (((seg * 4 + 2) ^ rm) << 4));
        float4 f3 = *(const float4*)(base + (((seg * 4 + 3) ^ rm) << 4));
        __half2 h0 = __floats2half2_rn(f0.x, f0.y);
        __half2 h1 = __floats2half2_rn(f0.z, f0.w);
        __half2 h2 = __floats2half2_rn(f1.x, f1.y);
        __half2 h3 = __floats2half2_rn(f1.z, f1.w);
        __half2 h4 = __floats2half2_rn(f2.x, f2.y);
        __half2 h5 = __floats2half2_rn(f2.z, f2.w);
        __half2 h6 = __floats2half2_rn(f3.x, f3.y);
        __half2 h7 = __floats2half2_rn(f3.z, f3.w);
        uint4 p0, p1;
        p0.x = *(uint32_t*)&h0; p0.y = *(uint32_t*)&h1;
        p0.z = *(uint32_t*)&h2; p0.w = *(uint32_t*)&h3;
        p1.x = *(uint32_t*)&h4; p1.y = *(uint32_t*)&h5;
        p1.z = *(uint32_t*)&h6; p1.w = *(uint32_t*)&h7;
        char* d = smem + O_B16 + (c & 3) * SZ_T + rb * BPAD + seg * 32;
        *(uint4*)d = p0;
        *(uint4*)(d + 16) = p1;
    };
    auto compute = [&](int c) {
        const uint32_t bA = sb + O_A + (c & 3) * SZ_T + aRowOff;
        const uint32_t bB = sb + O_B16 + (c & 3) * SZ_T + bRowOff;
#pragma unroll
        for (int ks = 0; ks < 2; ks++) {
            uint32_t a[2][4], b[4][4];
            ldm4(a[0], bA + ks * 32);
            ldm4(a[1], bA + 16 * BPAD + ks * 32);
#pragma unroll
            for (int p = 0; p < 4; p++) ldm4(b[p], bB + p * 16 * BPAD + ks * 32);
#pragma unroll
            for (int mt = 0; mt < 2; mt++)
#pragma unroll
                for (int nt = 0; nt < 8; nt++)
                    mma_f16(acc[mt][nt], a[mt], &b[nt >> 1][(nt & 1) * 2]);
        }
    };

    // ---- prologue: land chunks 0,1; convert both ----
    cpA(0); cpA(1); cpB(0); cpB(1);
    CP_COMMIT();
    CP_WAIT0();
    __syncthreads();          // A tiles visible to all
    convertB(0);
    convertB(1);
    __syncthreads();          // B16 tiles visible to all

    // ---- main loop: one wait + one barrier per 2 chunks ----
    const int S = nch >> 1;
    for (int s = 0; s < S; s++) {
        const int c0 = 2 * s;
        if (c0 + 2 < nch) { cpA(c0 + 2); cpB(c0 + 2); }
        if (c0 + 3 < nch) { cpA(c0 + 3); cpB(c0 + 3); }
        CP_COMMIT();
        compute(c0);
        compute(c0 + 1);
        CP_WAIT0();
        if (c0 + 2 < nch) convertB(c0 + 2);
        if (c0 + 3 < nch) convertB(c0 + 3);
        __syncthreads();
    }

    // ---- epilogue ----
    const int qr = lane >> 2, qc = (lane & 3) * 2;
#pragma unroll
    for (int mt = 0; mt < 2; mt++) {
        const int row = wm * 32 + mt * 16 + qr;
#pragma unroll
        for (int nt = 0; nt < 8; nt++) {
            const int col = n0 + wn * 64 + nt * 8 + qc;
            float2 v0; v0.x = acc[mt][nt][0]; v0.y = acc[mt][nt][1];
            float2 v1; v1.x = acc[mt][nt][2]; v1.y = acc[mt][nt][3];
            *(float2*)(out + (size_t)row * NQ + col) = v0;
            *(float2*)(out + (size_t)(row + 8) * NQ + col) = v1;
        }
    }
}

// ---------------- per-row reduction: 4 blocks per row (quarter-Q each) ----------------
__global__ __launch_bounds__(256) void row_reduce(
    const float* __restrict__ old_embeds, const float* __restrict__ feat_queue,
    const int* __restrict__ labels, const int* __restrict__ hdrp)
{
    const int i = blockIdx.x >> 2, quarter = blockIdx.x & 3, tid = threadIdx.x;
    const int lbl = labels[i];
    const int hdr = *hdrp;
    const int j0 = quarter * (NQ / 4);
    const float4* s1r = (const float4*)(g_s1 + (size_t)i * NQ + j0);
    const float4* s2r = (const float4*)(g_s2 + (size_t)i * NQ + j0);
    const int4*   ql4 = (const int4*)(g_qlab + j0);
    const float* oei = old_embeds + (size_t)i * DDIM;
    constexpr int NV = (NQ / 4) / 4;     // 2048

    float m1 = -INFINITY, m2 = -INFINITY;
    for (int v = tid; v < NV; v += 256) {
        float4 a = s1r[v], b = s2r[v];
        m1 = fmaxf(fmaxf(fmaxf(m1, a.x), fmaxf(a.y, a.z)), a.w);
        m2 = fmaxf(fmaxf(fmaxf(m2, b.x), fmaxf(b.y, b.z)), b.w);
    }
    for (int o = 16; o; o >>= 1) {
        m1 = fmaxf(m1, __shfl_xor_sync(0xffffffffu, m1, o));
        m2 = fmaxf(m2, __shfl_xor_sync(0xffffffffu, m2, o));
    }
    __shared__ float shm1[8], shm2[8];
    if ((tid & 31) == 0) { shm1[tid >> 5] = m1; shm2[tid >> 5] = m2; }
    __syncthreads();
    float M1 = shm1[0], M2 = shm2[0];
    for (int w = 1; w < 8; w++) { M1 = fmaxf(M1, shm1[w]); M2 = fmaxf(M2, shm2[w]); }

    float l1 = 0.f, l2 = 0.f, sw = 0.f, s1w = 0.f, s2w = 0.f, cnt = 0.f;
    for (int v = tid; v < NV; v += 256) {
        float4 a = s1r[v], b = s2r[v];
        l1 += __expf(a.x - M1) + __expf(a.y - M1) + __expf(a.z - M1) + __expf(a.w - M1);
        l2 += __expf(b.x - M2) + __expf(b.y - M2) + __expf(b.z - M2) + __expf(b.w - M2);
        int4 q = ql4[v];
        if (q.x == lbl || q.y == lbl || q.z == lbl || q.w == lbl) {
            const float va[4] = {a.x, a.y, a.z, a.w};
            const float vb[4] = {b.x, b.y, b.z, b.w};
            const int   qq[4] = {q.x, q.y, q.z, q.w};
#pragma unroll
            for (int e = 0; e < 4; e++) {
                if (qq[e] != lbl) continue;
                int jj = j0 + v * 4 + e;
                int r = (jj - hdr) & (NQ - 1);
                const float* frow = (r < NROW) ? (old_embeds + (size_t)r * DDIM)
                                               : (feat_queue + (size_t)jj * DDIM);
                float dot = 0.f;
#pragma unroll 8
                for (int d = 0; d < DDIM; d++) dot = fmaf(oei[d], frow[d], dot);
                float w = 0.5f * (dot + 1.0f);
                sw += w; s1w += w * va[e]; s2w += w * vb[e]; cnt += 1.f;
            }
        }
    }
    for (int o = 16; o; o >>= 1) {
        l1  += __shfl_down_sync(0xffffffffu, l1, o);
        l2  += __shfl_down_sync(0xffffffffu, l2, o);
        sw  += __shfl_down_sync(0xffffffffu, sw, o);
        s1w += __shfl_down_sync(0xffffffffu, s1w, o);
        s2w += __shfl_down_sync(0xffffffffu, s2w, o);
        cnt += __shfl_down_sync(0xffffffffu, cnt, o);
    }
    __shared__ float shl1[8], shl2[8], shsw[8], shs1[8], shs2[8], shc[8];
    if ((tid & 31) == 0) {
        int w = tid >> 5;
        shl1[w] = l1; shl2[w] = l2; shsw[w] = sw; shs1[w] = s1w; shs2[w] = s2w; shc[w] = cnt;
    }
    __syncthreads();
    if (tid == 0) {
        float L1 = 0, L2 = 0, SW = 0, S1 = 0, S2 = 0, CN = 0;
        for (int w = 0; w < 8; w++) {
            L1 += shl1[w]; L2 += shl2[w]; SW += shsw[w];
            S1 += shs1[w]; S2 += shs2[w]; CN += shc[w];
        }
        float* p = g_part + blockIdx.x * 8;
        p[0] = M1; p[1] = L1; p[2] = M2; p[3] = L2;
        p[4] = SW; p[5] = S1; p[6] = S2; p[7] = CN;
    }
}

// ---------------- finalize: merge 4 quarters per row ----------------
__global__ void finalize(float* __restrict__ out) {
    int tid = threadIdx.x;   // 128 threads, one row each
    float M1 = -INFINITY, M2 = -INFINITY;
#pragma unroll
    for (int q = 0; q < 4; q++) {
        const float* p = g_part + (4 * tid + q) * 8;
        M1 = fmaxf(M1, p[0]);
        M2 = fmaxf(M2, p[2]);
    }
    float L1 = 0, L2 = 0, SW = 0, S1 = 0, S2 = 0, CN = 0;
#pragma unroll
    for (int q = 0; q < 4; q++) {
        const float* p = g_part + (4 * tid + q) * 8;
        L1 += p[1] * __expf(p[0] - M1);
        L2 += p[3] * __expf(p[2] - M2);
        SW += p[4]; S1 += p[5]; S2 += p[6]; CN += p[7];
    }
    float lse1 = M1 + logf(L1);
    float lse2 = M2 + logf(L2);
    float ic = 1.0f / CN;
    float t1 = (S1 - lse1 * SW) * ic;
    float t2 = (S2 - lse2 * SW) * ic;
    for (int o = 16; o; o >>= 1) {
        t1 += __shfl_down_sync(0xffffffffu, t1, o);
        t2 += __shfl_down_sync(0xffffffffu, t2, o);
    }
    __shared__ float sh1[4], sh2[4];
    if ((tid & 31) == 0) { sh1[tid >> 5] = t1; sh2[tid >> 5] = t2; }
    __syncthreads();
    if (tid == 0) {
        out[0] = -(sh1[0] + sh1[1] + sh1[2] + sh1[3]) / (float)NROW;
        out[1] = -(sh2[0] + sh2[1] + sh2[2] + sh2[3]) / (float)NROW;
    }
}

// ---------------- launch ----------------
extern "C" void kernel_launch(void* const* d_in, const int* in_sizes, int n_in,
                              void* d_out, int out_size) {
    const float* old_embeds   = (const float*)d_in[0];
    const float* old_logits   = (const float*)d_in[1];
    const float* new_embeds   = (const float*)d_in[2];
    const float* new_logits   = (const float*)d_in[3];
    const int*   labels       = (const int*)d_in[4];
    const float* feat_queue   = (const float*)d_in[5];
    const float* logit_queue  = (const float*)d_in[6];
    const int*   queue_labels = (const int*)d_in[7];
    const int*   header       = (const int*)d_in[8];
    float* out = (float*)d_out;

    unsigned short *p_a1, *p_a2;
    float *p_s1, *p_s2;
    cudaGetSymbolAddress((void**)&p_a1, g_a1);
    cudaGetSymbolAddress((void**)&p_a2, g_a2);
    cudaGetSymbolAddress((void**)&p_s1, g_s1);
    cudaGetSymbolAddress((void**)&p_s2, g_s2);

    cudaFuncSetAttribute(gemm_mma, cudaFuncAttributeMaxDynamicSharedMemorySize, GEMM_SMEM);

    normalize_half<<<NROW, 128>>>(new_embeds);
    half_logits<<<(NROW * CDIM) / (256 * 4), 256>>>(new_logits);
    build_qlab<<<NQ / 256, 256>>>(queue_labels, labels, header);

    // fused: blocks [0,256) -> l1 GEMM (K=DDIM, short), [256,512) -> l2 GEMM (K=CDIM)
    gemm_mma<<<512, 256, GEMM_SMEM>>>(p_a1, feat_queue, old_embeds, p_s1, DDIM,
                                      p_a2, logit_queue, old_logits, p_s2, CDIM,
                                      header);

    row_reduce<<<4 * NROW, 256>>>(old_embeds, feat_queue, labels, header);
    finalize<<<1, 128>>>(out);
}

// round 13
// speedup vs baseline: 1.2555x; 1.2555x over previous
#include <cuda_runtime.h>
#include <cuda_fp16.h>
#include <cstdint>
#include <math.h>

// Shapes (fixed)
constexpr int NROW = 128;
constexpr int DDIM = 512;
constexpr int CDIM = 8192;
constexpr int NQ   = 32768;

// ---------------- device scratch ----------------
__device__ __align__(16) float g_s1[(size_t)NROW * NQ];
__device__ __align__(16) float g_s2[(size_t)NROW * NQ];    // l2 scores, K-slice 0
__device__ __align__(16) float g_s2b[(size_t)NROW * NQ];   // l2 scores, K-slice 1
__device__ __align__(16) unsigned short g_a1[NROW * DDIM]; // fp16 normalized new_embeds
__device__ __align__(16) unsigned short g_a2[NROW * CDIM]; // fp16 new_logits
__device__ int   g_qlab[NQ];
__device__ float g_part[256 * 8];     // per (row, half): m1,l1,m2,l2,sw,s1w,s2w,cnt

// ---------------- small helpers ----------------
__device__ __forceinline__ uint32_t smem_u32(const void* p) {
    uint32_t a;
    asm("{ .reg .u64 t; cvta.to.shared.u64 t, %1; cvt.u32.u64 %0, t; }" : "=r"(a) : "l"(p));
    return a;
}
__device__ __forceinline__ void ldm4(uint32_t* r, uint32_t addr) {
    asm volatile("ldmatrix.sync.aligned.m8n8.x4.shared.b16 {%0,%1,%2,%3}, [%4];"
                 : "=r"(r[0]), "=r"(r[1]), "=r"(r[2]), "=r"(r[3]) : "r"(addr));
}
__device__ __forceinline__ void mma_f16(float* d, const uint32_t* a, const uint32_t* b) {
    asm volatile(
        "mma.sync.aligned.m16n8k16.row.col.f32.f16.f16.f32 "
        "{%0,%1,%2,%3}, {%4,%5,%6,%7}, {%8,%9}, {%0,%1,%2,%3};"
        : "+f"(d[0]), "+f"(d[1]), "+f"(d[2]), "+f"(d[3])
        : "r"(a[0]), "r"(a[1]), "r"(a[2]), "r"(a[3]), "r"(b[0]), "r"(b[1]));
}
#define CP16(saddr, gptr) \
    asm volatile("cp.async.ca.shared.global [%0], [%1], 16;" :: "r"(saddr), "l"(gptr))
#define CP_COMMIT() asm volatile("cp.async.commit_group;" ::: "memory")
#define CP_WAIT0()  asm volatile("cp.async.wait_group 0;" ::: "memory")

// ---------------- kernel: normalize new_embeds -> fp16 ----------------
__global__ void normalize_half(const float* __restrict__ x) {
    int i = blockIdx.x, tid = threadIdx.x;           // 128 threads
    const float* xr = x + (size_t)i * DDIM;
    float s = 0.f;
    for (int d = tid; d < DDIM; d += 128) { float v = xr[d]; s += v * v; }
    for (int o = 16; o; o >>= 1) s += __shfl_down_sync(0xffffffffu, s, o);
    __shared__ float sh[4];
    if ((tid & 31) == 0) sh[tid >> 5] = s;
    __syncthreads();
    __shared__ float invs;
    if (tid == 0) invs = 1.0f / fmaxf(sqrtf(sh[0] + sh[1] + sh[2] + sh[3]), 1e-12f);
    __syncthreads();
    float iv = invs;
    for (int d = tid; d < DDIM; d += 128)
        g_a1[i * DDIM + d] = __half_as_ushort(__float2half_rn(xr[d] * iv));
}

// ---------------- kernel: new_logits -> fp16 ----------------
__global__ void half_logits(const float* __restrict__ x) {
    int idx = (blockIdx.x * blockDim.x + threadIdx.x) * 4;   // over 128*8192
    float4 v = *(const float4*)(x + idx);
    __half2 h0 = __floats2half2_rn(v.x, v.y);
    __half2 h1 = __floats2half2_rn(v.z, v.w);
    uint2 p; p.x = *(uint32_t*)&h0; p.y = *(uint32_t*)&h1;
    *(uint2*)(g_a2 + idx) = p;
}

// ---------------- kernel: updated queue labels ----------------
__global__ void build_qlab(const int* __restrict__ ql, const int* __restrict__ labels,
                           const int* __restrict__ hdrp) {
    int j = blockIdx.x * blockDim.x + threadIdx.x;
    int hdr = *hdrp;
    int r = (j - hdr) & (NQ - 1);
    g_qlab[j] = (r < NROW) ? labels[r] : ql[j];
}

// ---------------- fused fp16 GEMMs: cp.async staging, convert-in-compute, split-K l2 ----
// blocks [0,256):   l2, K-slice 0 (K rows [0,4096))    -> g_s2
// blocks [256,512): l2, K-slice 1 (K rows [4096,8192)) -> g_s2b
// blocks [512,768): l1 (K=512)                         -> g_s1
// CTA tile 128x128, BK=32; 8 warps (4M x 2N), warp tile 32x64.
constexpr int BPAD = 80;                 // fp16 tile row stride (conflict-free ldmatrix)
constexpr int FSTR = 144;                // fp32 staging row stride (128B data + 16B pad)
constexpr int SZ_T = 128 * BPAD;         // 10240
constexpr int SZ_F = 128 * FSTR;         // 18432
constexpr int O_A   = 0;                 // [2 stages x 10240]
constexpr int O_B16 = 2 * SZ_T;          // 20480 [2 stages x 10240]
constexpr int O_FS  = 4 * SZ_T;          // 40960 [2 stages x 18432]
constexpr int GEMM_SMEM = O_FS + 2 * SZ_F;   // 77824 -> 2 CTAs/SM

__global__ __launch_bounds__(256, 2) void gemm_mma(
    const float* __restrict__ Bq2, const float* __restrict__ Bold2,
    const float* __restrict__ Bq1, const float* __restrict__ Bold1,
    const int* __restrict__ hdrp)
{
    extern __shared__ char smem[];
    const uint32_t sb = smem_u32(smem);
    const int tid = threadIdx.x, lane = tid & 31, wid = tid >> 5;
    const int wm = wid >> 1, wn = wid & 1;
    const int bidx = blockIdx.x;

    // select problem / K-slice
    const unsigned short* A;
    const float *Bq, *Bold;
    float* out;
    int K, koff, n0, nch;
    if (bidx < 512) {                        // l2 (split-K x2)
        A = g_a2; Bq = Bq2; Bold = Bold2; K = CDIM;
        const int slice = bidx >> 8;         // 0 or 1
        koff = slice * (CDIM / 2);
        out = slice ? g_s2b : g_s2;
        n0 = (bidx & 255) * 128;
        nch = (CDIM / 2) >> 5;               // 128
    } else {                                 // l1
        A = g_a1; Bq = Bq1; Bold = Bold1; K = DDIM;
        koff = 0;
        out = g_s1;
        n0 = (bidx - 512) * 128;
        nch = DDIM >> 5;                     // 16
    }

    // B gmem row with circular-queue redirect; 2 threads per row, 64B (16 fp32) each
    const int rb = tid >> 1, seg = tid & 1;
    const int hdr = *hdrp;
    const int j = n0 + rb;
    const int r = (j - hdr) & (NQ - 1);
    const char* gB = (const char*)(((r < NROW) ? (Bold + (size_t)r * K)
                                               : (Bq + (size_t)j * K)) + koff + seg * 16);

    // A: 2 threads per row, 32B each (row = 64B fp16 per chunk)
    const int arow = tid >> 1;
    const int acol = (tid & 1) * 32;
    const char* gA = (const char*)A + (size_t)arow * K * 2 + koff * 2 + acol;
    const uint32_t sA = sb + O_A + arow * BPAD + acol;

    // ldmatrix lane addressing
    const int g = lane >> 3, lr = lane & 7;
    const uint32_t aRowOff = (uint32_t)(wm * 32 + (g & 1) * 8 + lr) * BPAD + (g >> 1) * 16;
    const uint32_t bRowOff = (uint32_t)(wn * 64 + (g >> 1) * 8 + lr) * BPAD + (g & 1) * 16;

    float acc[2][8][4];
#pragma unroll
    for (int mt = 0; mt < 2; mt++)
#pragma unroll
        for (int nt = 0; nt < 8; nt++)
#pragma unroll
            for (int u = 0; u < 4; u++) acc[mt][nt][u] = 0.f;

    auto cpA = [&](int c, int st) {
        const char* s0 = gA + (size_t)c * 64;
        uint32_t d0 = sA + st * SZ_T;
        CP16(d0, s0); CP16(d0 + 16, s0 + 16);
    };
    auto cpB = [&](int c, int st) {
        const char* s0 = gB + (size_t)c * 128;
        uint32_t d0 = sb + O_FS + st * SZ_F + rb * FSTR + seg * 64;
#pragma unroll
        for (int i = 0; i < 4; i++) CP16(d0 + 16 * i, s0 + 16 * i);
    };
    // convert chunk staged in fp32 stage st2 -> fp16 tile stage st2
    auto convertB = [&](int st2) {
        const char* src = smem + O_FS + st2 * SZ_F + rb * FSTR + seg * 64;
        float4 f0 = *(const float4*)(src);
        float4 f1 = *(const float4*)(src + 16);
        float4 f2 = *(const float4*)(src + 32);
        float4 f3 = *(const float4*)(src + 48);
        __half2 h0 = __floats2half2_rn(f0.x, f0.y);
        __half2 h1 = __floats2half2_rn(f0.z, f0.w);
        __half2 h2 = __floats2half2_rn(f1.x, f1.y);
        __half2 h3 = __floats2half2_rn(f1.z, f1.w);
        __half2 h4 = __floats2half2_rn(f2.x, f2.y);
        __half2 h5 = __floats2half2_rn(f2.z, f2.w);
        __half2 h6 = __floats2half2_rn(f3.x, f3.y);
        __half2 h7 = __floats2half2_rn(f3.z, f3.w);
        uint4 p0, p1;
        p0.x = *(uint32_t*)&h0; p0.y = *(uint32_t*)&h1;
        p0.z = *(uint32_t*)&h2; p0.w = *(uint32_t*)&h3;
        p1.x = *(uint32_t*)&h4; p1.y = *(uint32_t*)&h5;
        p1.z = *(uint32_t*)&h6; p1.w = *(uint32_t*)&h7;
        char* d = smem + O_B16 + st2 * SZ_T + rb * BPAD + seg * 32;
        *(uint4*)d = p0;
        *(uint4*)(d + 16) = p1;
    };
    // compute chunk c (stage st); if conv, convert next chunk's B between ks=0 and ks=1
    auto computeConv = [&](int c, bool conv) {
        const int st = c & 1;
        const uint32_t bA = sb + O_A + st * SZ_T + aRowOff;
        const uint32_t bB = sb + O_B16 + st * SZ_T + bRowOff;
        {   // ks = 0
            uint32_t a[2][4], b[4][4];
            ldm4(a[0], bA);
            ldm4(a[1], bA + 16 * BPAD);
#pragma unroll
            for (int p = 0; p < 4; p++) ldm4(b[p], bB + p * 16 * BPAD);
#pragma unroll
            for (int mt = 0; mt < 2; mt++)
#pragma unroll
                for (int nt = 0; nt < 8; nt++)
                    mma_f16(acc[mt][nt], a[mt], &b[nt >> 1][(nt & 1) * 2]);
        }
        if (conv) convertB(st ^ 1);          // hidden under ks=0 MMA drain
        {   // ks = 1
            uint32_t a[2][4], b[4][4];
            ldm4(a[0], bA + 32);
            ldm4(a[1], bA + 16 * BPAD + 32);
#pragma unroll
            for (int p = 0; p < 4; p++) ldm4(b[p], bB + p * 16 * BPAD + 32);
#pragma unroll
            for (int mt = 0; mt < 2; mt++)
#pragma unroll
                for (int nt = 0; nt < 8; nt++)
                    mma_f16(acc[mt][nt], a[mt], &b[nt >> 1][(nt & 1) * 2]);
        }
    };

    // ---- prologue: land B(0), B(1), A(0); convert B(0) ----
    cpB(0, 0);
    cpB(1, 1);
    cpA(0, 0);
    CP_COMMIT();
    CP_WAIT0();
    __syncthreads();
    convertB(0);
    __syncthreads();

    // ---- main loop: one wait + one barrier per chunk; convert inside compute ----
    for (int c = 0; c < nch; c++) {
        const int st = c & 1;
        if (c > 0) { CP_WAIT0(); __syncthreads(); }
        if (c + 2 < nch) cpB(c + 2, st);      // old B(c) staging: converted last iter
        if (c + 1 < nch) cpA(c + 1, st ^ 1);
        CP_COMMIT();
        computeConv(c, c + 1 < nch);
    }

    // ---- epilogue ----
    const int qr = lane >> 2, qc = (lane & 3) * 2;
#pragma unroll
    for (int mt = 0; mt < 2; mt++) {
        const int row = wm * 32 + mt * 16 + qr;
#pragma unroll
        for (int nt = 0; nt < 8; nt++) {
            const int col = n0 + wn * 64 + nt * 8 + qc;
            float2 v0; v0.x = acc[mt][nt][0]; v0.y = acc[mt][nt][1];
            float2 v1; v1.x = acc[mt][nt][2]; v1.y = acc[mt][nt][3];
            *(float2*)(out + (size_t)row * NQ + col) = v0;
            *(float2*)(out + (size_t)(row + 8) * NQ + col) = v1;
        }
    }
}

// ---------------- per-row reduction: 2 blocks per row (half-Q each) ----------------
__global__ __launch_bounds__(256) void row_reduce(
    const float* __restrict__ old_embeds, const float* __restrict__ feat_queue,
    const int* __restrict__ labels, const int* __restrict__ hdrp)
{
    const int i = blockIdx.x >> 1, half = blockIdx.x & 1, tid = threadIdx.x;
    const int lbl = labels[i];
    const int hdr = *hdrp;
    const int j0 = half * (NQ / 2);
    const float4* s1r  = (const float4*)(g_s1  + (size_t)i * NQ + j0);
    const float4* s2r  = (const float4*)(g_s2  + (size_t)i * NQ + j0);
    const float4* s2br = (const float4*)(g_s2b + (size_t)i * NQ + j0);
    const int4*   ql4  = (const int4*)(g_qlab + j0);
    const float* oei = old_embeds + (size_t)i * DDIM;
    constexpr int NV = (NQ / 2) / 4;

    float m1 = -INFINITY, m2 = -INFINITY;
    for (int v = tid; v < NV; v += 256) {
        float4 a = s1r[v];
        float4 b = s2r[v], bb = s2br[v];
        b.x += bb.x; b.y += bb.y; b.z += bb.z; b.w += bb.w;
        m1 = fmaxf(fmaxf(fmaxf(m1, a.x), fmaxf(a.y, a.z)), a.w);
        m2 = fmaxf(fmaxf(fmaxf(m2, b.x), fmaxf(b.y, b.z)), b.w);
    }
    for (int o = 16; o; o >>= 1) {
        m1 = fmaxf(m1, __shfl_xor_sync(0xffffffffu, m1, o));
        m2 = fmaxf(m2, __shfl_xor_sync(0xffffffffu, m2, o));
    }
    __shared__ float shm1[8], shm2[8];
    if ((tid & 31) == 0) { shm1[tid >> 5] = m1; shm2[tid >> 5] = m2; }
    __syncthreads();
    float M1 = shm1[0], M2 = shm2[0];
    for (int w = 1; w < 8; w++) { M1 = fmaxf(M1, shm1[w]); M2 = fmaxf(M2, shm2[w]); }

    float l1 = 0.f, l2 = 0.f, sw = 0.f, s1w = 0.f, s2w = 0.f, cnt = 0.f;
    for (int v = tid; v < NV; v += 256) {
        float4 a = s1r[v];
        float4 b = s2r[v], bb = s2br[v];
        b.x += bb.x; b.y += bb.y; b.z += bb.z; b.w += bb.w;
        l1 += __expf(a.x - M1) + __expf(a.y - M1) + __expf(a.z - M1) + __expf(a.w - M1);
        l2 += __expf(b.x - M2) + __expf(b.y - M2) + __expf(b.z - M2) + __expf(b.w - M2);
        int4 q = ql4[v];
        if (q.x == lbl || q.y == lbl || q.z == lbl || q.w == lbl) {
            const float va[4] = {a.x, a.y, a.z, a.w};
            const float vb[4] = {b.x, b.y, b.z, b.w};
            const int   qq[4] = {q.x, q.y, q.z, q.w};
#pragma unroll
            for (int e = 0; e < 4; e++) {
                if (qq[e] != lbl) continue;
                int jj = j0 + v * 4 + e;
                int r = (jj - hdr) & (NQ - 1);
                const float* frow = (r < NROW) ? (old_embeds + (size_t)r * DDIM)
                                               : (feat_queue + (size_t)jj * DDIM);
                float dot = 0.f;
#pragma unroll 8
                for (int d = 0; d < DDIM; d++) dot = fmaf(oei[d], frow[d], dot);
                float w = 0.5f * (dot + 1.0f);
                sw += w; s1w += w * va[e]; s2w += w * vb[e]; cnt += 1.f;
            }
        }
    }
    for (int o = 16; o; o >>= 1) {
        l1  += __shfl_down_sync(0xffffffffu, l1, o);
        l2  += __shfl_down_sync(0xffffffffu, l2, o);
        sw  += __shfl_down_sync(0xffffffffu, sw, o);
        s1w += __shfl_down_sync(0xffffffffu, s1w, o);
        s2w += __shfl_down_sync(0xffffffffu, s2w, o);
        cnt += __shfl_down_sync(0xffffffffu, cnt, o);
    }
    __shared__ float shl1[8], shl2[8], shsw[8], shs1[8], shs2[8], shc[8];
    if ((tid & 31) == 0) {
        int w = tid >> 5;
        shl1[w] = l1; shl2[w] = l2; shsw[w] = sw; shs1[w] = s1w; shs2[w] = s2w; shc[w] = cnt;
    }
    __syncthreads();
    if (tid == 0) {
        float L1 = 0, L2 = 0, SW = 0, S1 = 0, S2 = 0, CN = 0;
        for (int w = 0; w < 8; w++) {
            L1 += shl1[w]; L2 += shl2[w]; SW += shsw[w];
            S1 += shs1[w]; S2 += shs2[w]; CN += shc[w];
        }
        float* p = g_part + blockIdx.x * 8;
        p[0] = M1; p[1] = L1; p[2] = M2; p[3] = L2;
        p[4] = SW; p[5] = S1; p[6] = S2; p[7] = CN;
    }
}

// ---------------- finalize ----------------
__global__ void finalize(float* __restrict__ out) {
    int tid = threadIdx.x;   // 128 threads, one row each
    const float* pa = g_part + (2 * tid) * 8;
    const float* pb = g_part + (2 * tid + 1) * 8;
    float M1 = fmaxf(pa[0], pb[0]);
    float L1 = pa[1] * __expf(pa[0] - M1) + pb[1] * __expf(pb[0] - M1);
    float M2 = fmaxf(pa[2], pb[2]);
    float L2 = pa[3] * __expf(pa[2] - M2) + pb[3] * __expf(pb[2] - M2);
    float SW = pa[4] + pb[4];
    float S1 = pa[5] + pb[5];
    float S2 = pa[6] + pb[6];
    float CN = pa[7] + pb[7];
    float lse1 = M1 + logf(L1);
    float lse2 = M2 + logf(L2);
    float ic = 1.0f / CN;
    float t1 = (S1 - lse1 * SW) * ic;
    float t2 = (S2 - lse2 * SW) * ic;
    for (int o = 16; o; o >>= 1) {
        t1 += __shfl_down_sync(0xffffffffu, t1, o);
        t2 += __shfl_down_sync(0xffffffffu, t2, o);
    }
    __shared__ float sh1[4], sh2[4];
    if ((tid & 31) == 0) { sh1[tid >> 5] = t1; sh2[tid >> 5] = t2; }
    __syncthreads();
    if (tid == 0) {
        out[0] = -(sh1[0] + sh1[1] + sh1[2] + sh1[3]) / (float)NROW;
        out[1] = -(sh2[0] + sh2[1] + sh2[2] + sh2[3]) / (float)NROW;
    }
}

// ---------------- launch ----------------
extern "C" void kernel_launch(void* const* d_in, const int* in_sizes, int n_in,
                              void* d_out, int out_size) {
    const float* old_embeds   = (const float*)d_in[0];
    const float* old_logits   = (const float*)d_in[1];
    const float* new_embeds   = (const float*)d_in[2];
    const float* new_logits   = (const float*)d_in[3];
    const int*   labels       = (const int*)d_in[4];
    const float* feat_queue   = (const float*)d_in[5];
    const float* logit_queue  = (const float*)d_in[6];
    const int*   queue_labels = (const int*)d_in[7];
    const int*   header       = (const int*)d_in[8];
    float* out = (float*)d_out;

    cudaFuncSetAttribute(gemm_mma, cudaFuncAttributeMaxDynamicSharedMemorySize, GEMM_SMEM);

    normalize_half<<<NROW, 128>>>(new_embeds);
    half_logits<<<(NROW * CDIM) / (256 * 4), 256>>>(new_logits);
    build_qlab<<<NQ / 256, 256>>>(queue_labels, labels, header);

    // fused: [0,512) l2 split-K x2, [512,768) l1
    gemm_mma<<<768, 256, GEMM_SMEM>>>(logit_queue, old_logits,
                                      feat_queue, old_embeds, header);

    row_reduce<<<2 * NROW, 256>>>(old_embeds, feat_queue, labels, header);
    finalize<<<1, 128>>>(out);
}